// round 10
// baseline (speedup 1.0000x reference)
#include <cuda_runtime.h>
#include <cuda_fp16.h>

// LearnableShiftViews: out[v,b,c,h,w] = separable bilinear resample of x[b,c]
// at pix = (idx + d)*size/(size-1) - 0.5 per axis, zero padding.
//
// R10 (base = R9): two compounding changes.
//  1) Diff-packed fp16 pair table: entry p = half2(data[p-2], data[p-1]-data[p-2]),
//     so the x-lerp is a single fmaf(fx, da, a0) in fp32 (2 FADD/output deleted).
//     Skewed addressing addr(e) = e + (e>>5) keeps the quad-thread stride-4
//     access conflict-free.
//  2) Stores leave the LSU: each thread STS.128s its 4 outputs into a per-view
//     smem slab (5 disjoint slabs, no inter-view syncs); after one final
//     __syncthreads, thread 0 ships each 7168-byte contiguous slab to GMEM
//     with cp.async.bulk (TMA), removing the STG issue cost (the largest
//     single L1/LSU term) from the warp instruction stream.
// Pads: entries for out-of-range taps hold exact zeros / masked forms, so the
// blend needs no masks. Weights & blend fp32; taps+deltas fp16 (rel ~4e-4).

namespace {

constexpr int H = 224;
constexpr int W = 224;
constexpr int B = 64;
constexpr int C = 3;
constexpr int BCN = B * C;     // 192
constexpr int V = 5;
constexpr int TILE_Y = 8;
constexpr int ROWS_CAP = 12;   // canonical |dy|<=1 needs at most 12 staged rows
constexpr int NTHREADS = 224;  // 56 quads x 4 rows per pass
constexpr int CH4 = W / 4;     // 56 float4 chunks per input row
constexpr int SRS = 236;       // skewed words per packed row
constexpr int OB_BYTES = TILE_Y * W * 4;   // 7168 B per view slab

__device__ __forceinline__ int skew(int e) { return e + (e >> 5); }

__device__ __forceinline__ unsigned smem_u32(const void* p) {
    unsigned a;
    asm("{ .reg .u64 t; cvta.to.shared.u64 t, %1; cvt.u32.u64 %0, t; }"
        : "=r"(a) : "l"(p));
    return a;
}

__global__ __launch_bounds__(NTHREADS)
void shift_views_kernel(const float* __restrict__ x,
                        const float* __restrict__ offs,
                        float* __restrict__ out) {
    __shared__ __half2 spack[ROWS_CAP * SRS];                 // 11.3 KB
    __shared__ float4  ycoef[V][TILE_Y];                      // 640 B
    __shared__ __align__(16) float obuf[V][TILE_Y * W];       // 35 KB

    const int yb  = blockIdx.x * TILE_Y;
    const int bc  = blockIdx.y;
    const int tid = threadIdx.x;
    const float sy = (float)H / (float)(H - 1);
    const float sx = (float)W / (float)(W - 1);

    // ---- Row range needed across all views (endpoints suffice; monotone).
    int rmin = H - 1, rmax = 0;
#pragma unroll
    for (int v = 0; v < V; ++v) {
        float dy = __ldg(&offs[2 * v]);
        int lo = (int)floorf(((float)yb + dy) * sy - 0.5f);
        int hi = (int)floorf(((float)(yb + TILE_Y - 1) + dy) * sy - 0.5f) + 1;
        lo = max(lo, 0);
        hi = min(hi, H - 1);
        rmin = min(rmin, lo);
        rmax = max(rmax, hi);
    }
    if (rmin > rmax) { rmin = 0; rmax = 0; }
    rmax = min(rmax, rmin + ROWS_CAP - 1);
    const int nrows = rmax - rmin + 1;

    // ---- Build y-coefficient table: one thread per (v, ty).
    if (tid < V * TILE_Y) {
        int v  = tid >> 3;
        int t  = tid & 7;
        float dy   = offs[2 * v];
        float ypix = ((float)(yb + t) + dy) * sy - 0.5f;
        float py   = floorf(ypix);
        float fy   = ypix - py;
        int   iy0  = (int)py;
        float wy0  = ((unsigned)iy0       < (unsigned)H) ? (1.0f - fy) : 0.0f;
        float wy1  = ((unsigned)(iy0 + 1) < (unsigned)H) ? fy          : 0.0f;
        int r0 = min(max(iy0,     rmin), rmax) - rmin;
        int r1 = min(max(iy0 + 1, rmin), rmax) - rmin;
        ycoef[v][t] = make_float4(wy0, wy1,
                                  __int_as_float(r0 * SRS * 4),
                                  __int_as_float(r1 * SRS * 4));
    }

    // ---- Stage + pack skewed diff table: entry p = (data[p-2], data[p-1]-data[p-2]).
    {
        const float*  srcf = x + (size_t)bc * (H * W) + (size_t)rmin * W;
        const float4* src4 = reinterpret_cast<const float4*>(srcf);
        const int total = nrows * CH4;
        for (int i = tid; i < total; i += NTHREADS) {
            int r = i / CH4;
            int c = i - r * CH4;
            float4 g = src4[r * CH4 + c];
            float hi3 = (c == CH4 - 1) ? 0.0f : __ldg(srcf + r * W + 4 * c + 4);
            __half2* row = &spack[r * SRS];
            row[skew(4 * c + 2)] = __floats2half2_rn(g.x, g.y - g.x);
            row[skew(4 * c + 3)] = __floats2half2_rn(g.y, g.z - g.y);
            row[skew(4 * c + 4)] = __floats2half2_rn(g.z, g.w - g.z);
            row[skew(4 * c + 5)] = __floats2half2_rn(g.w, hi3 - g.w);
            if (c == 0) {                 // left pads: (0,0) and (0, data[0])
                row[skew(0)] = __floats2half2_rn(0.f, 0.f);
                row[skew(1)] = __floats2half2_rn(0.f, g.x);
            }
            if (c == CH4 - 1) {           // right pads
                row[skew(226)] = __floats2half2_rn(0.f, 0.f);
            }
        }
    }
    __syncthreads();

    // ---- Compute: thread = (row-in-pass r, quad q); outputs x = 4q..4q+3,
    // rows ty = r and r+4; 4 outputs stored with one STS.128 into obuf[v].
    const int r  = tid / 56;     // 0..3
    const int q  = tid - r * 56; // 0..55
    const int x0 = 4 * q;
    const char* sb = (const char*)spack;

#pragma unroll 1
    for (int v = 0; v < V; ++v) {
        const float dx = __ldg(&offs[2 * v + 1]);
        const float cx = dx * sx - 0.5f;

        float fxj[4];
        int   saj[4];
#pragma unroll
        for (int j = 0; j < 4; ++j) {
            float xpix = fmaf((float)(x0 + j), sx, cx);
            int   ix0  = __float2int_rd(xpix);
            fxj[j]     = xpix - (float)ix0;
            int   p0   = min(max(ix0 + 2, 0), 226);
            saj[j]     = skew(p0) * 4;            // skewed byte offset
        }

#pragma unroll
        for (int pass = 0; pass < 2; ++pass) {
            const int ty = r + 4 * pass;
            float4 yc = ycoef[v][ty];
            const char* rb0 = sb + __float_as_int(yc.z);
            const char* rb1 = sb + __float_as_int(yc.w);

            float4 res;
            float* rp = &res.x;
#pragma unroll
            for (int j = 0; j < 4; ++j) {
                __half2 h0 = *(const __half2*)(rb0 + saj[j]);
                __half2 h1 = *(const __half2*)(rb1 + saj[j]);
                float t0 = fmaf(fxj[j], __high2float(h0), __low2float(h0));
                float t1 = fmaf(fxj[j], __high2float(h1), __low2float(h1));
                rp[j] = fmaf(t1, yc.y, t0 * yc.x);
            }
            *reinterpret_cast<float4*>(&obuf[v][ty * W + x0]) = res;  // STS.128
        }
    }
    __syncthreads();   // all STS visible before TMA reads smem

    if (tid == 0) {
        asm volatile("fence.proxy.async.shared::cta;" ::: "memory");
#pragma unroll
        for (int v = 0; v < V; ++v) {
            float* dst = out + (((size_t)(v * BCN + bc)) * H + yb) * W;
            asm volatile(
                "cp.async.bulk.global.shared::cta.bulk_group [%0], [%1], %2;"
                :: "l"(dst), "r"(smem_u32(&obuf[v][0])), "n"(OB_BYTES) : "memory");
        }
        asm volatile("cp.async.bulk.commit_group;" ::: "memory");
        asm volatile("cp.async.bulk.wait_group 0;" ::: "memory");
    }
}

}  // namespace

extern "C" void kernel_launch(void* const* d_in, const int* in_sizes, int n_in,
                              void* d_out, int out_size) {
    const float* x    = (const float*)d_in[0];
    const float* offs = (const float*)d_in[1];
    if (n_in >= 2 && in_sizes[0] == 2 * V) {   // tolerate swapped metadata order
        const float* t = x; x = offs; offs = t;
    }
    dim3 grid(H / TILE_Y, BCN);
    shift_views_kernel<<<grid, NTHREADS>>>(x, offs, (float*)d_out);
}

// round 11
// speedup vs baseline: 1.2074x; 1.2074x over previous
#include <cuda_runtime.h>
#include <cuda_fp16.h>

// LearnableShiftViews: out[v,b,c,h,w] = separable bilinear resample of x[b,c]
// at pix = (idx + d)*size/(size-1) - 0.5 per axis, zero padding.
//
// R11 (base = R9, 53.2us, issue-bound at 82.7%): two issue cuts, keeping
// R9's high-occupancy STG.128 structure (R10 showed 35KB obuf kills occ).
//  1) Diff-packed fp16 pair table: entry p = half2(a0, a1-a0) so the x-lerp
//     is one fp32 fmaf (2 FADD/output removed). Pads verified in R10.
//  2) x-coefficients {fx, skewed byte-offset} tabulated per block in smem
//     (identical work was being recomputed per view per thread): read as 4
//     stride-1 conflict-free LDS.64 per view, amortized over 8 outputs.
// Table addressing stays skewed (addr = e + (e>>5) words) so the quad-thread
// stride-4 tap loads are bank-conflict-free. Weights/blend fp32; taps+deltas
// fp16 (rel_err ~3.3e-4 vs 1e-3 threshold).

namespace {

constexpr int H = 224;
constexpr int W = 224;
constexpr int B = 64;
constexpr int C = 3;
constexpr int BCN = B * C;     // 192
constexpr int V = 5;
constexpr int TILE_Y = 8;
constexpr int ROWS_CAP = 16;
constexpr int NTHREADS = 224;  // 56 quads x 4 rows per pass
constexpr int CH4 = W / 4;     // 56 float4 chunks per input row
constexpr int SRS = 236;       // skewed words per packed row
constexpr int NQ = W / 4;      // 56 quads per row

__device__ __forceinline__ int skew(int e) { return e + (e >> 5); }

__global__ __launch_bounds__(NTHREADS)
void shift_views_kernel(const float* __restrict__ x,
                        const float* __restrict__ offs,
                        float* __restrict__ out) {
    __shared__ __half2 spack[ROWS_CAP * SRS];   // skewed diff pair table, 15.1 KB
    __shared__ float4  ycoef[V][TILE_Y];        // {wy0, wy1, byteoff0, byteoff1}
    __shared__ float2  xtab[V][4][NQ];          // {fx, skewed byteoff}, 9 KB

    const int yb  = blockIdx.x * TILE_Y;
    const int bc  = blockIdx.y;
    const int tid = threadIdx.x;
    const float sy = (float)H / (float)(H - 1);
    const float sx = (float)W / (float)(W - 1);

    // ---- Row range needed across all views (endpoints suffice; monotone).
    int rmin = H - 1, rmax = 0;
#pragma unroll
    for (int v = 0; v < V; ++v) {
        float dy = __ldg(&offs[2 * v]);
        int lo = (int)floorf(((float)yb + dy) * sy - 0.5f);
        int hi = (int)floorf(((float)(yb + TILE_Y - 1) + dy) * sy - 0.5f) + 1;
        lo = max(lo, 0);
        hi = min(hi, H - 1);
        rmin = min(rmin, lo);
        rmax = max(rmax, hi);
    }
    if (rmin > rmax) { rmin = 0; rmax = 0; }
    rmax = min(rmax, rmin + ROWS_CAP - 1);
    const int nrows = rmax - rmin + 1;

    // ---- Build y-coefficient table: one thread per (v, ty).
    if (tid < V * TILE_Y) {
        int v  = tid >> 3;
        int t  = tid & 7;
        float dy   = offs[2 * v];
        float ypix = ((float)(yb + t) + dy) * sy - 0.5f;
        float py   = floorf(ypix);
        float fy   = ypix - py;
        int   iy0  = (int)py;
        float wy0  = ((unsigned)iy0       < (unsigned)H) ? (1.0f - fy) : 0.0f;
        float wy1  = ((unsigned)(iy0 + 1) < (unsigned)H) ? fy          : 0.0f;
        int r0 = min(max(iy0,     rmin), rmax) - rmin;
        int r1 = min(max(iy0 + 1, rmin), rmax) - rmin;
        ycoef[v][t] = make_float4(wy0, wy1,
                                  __int_as_float(r0 * SRS * 4),
                                  __int_as_float(r1 * SRS * 4));
    }

    // ---- Build x-coefficient table: thread tid handles x = tid, all views.
    if (tid < W) {
#pragma unroll
        for (int v = 0; v < V; ++v) {
            float dx   = __ldg(&offs[2 * v + 1]);
            float xpix = fmaf((float)tid, sx, dx * sx - 0.5f);
            int   ix0  = __float2int_rd(xpix);
            float fx   = xpix - (float)ix0;
            int   p0   = min(max(ix0 + 2, 0), 226);
            xtab[v][tid & 3][tid >> 2] =
                make_float2(fx, __int_as_float(skew(p0) * 4));
        }
    }

    // ---- Stage + pack skewed diff table: entry p = (a0, a1-a0).
    {
        const float*  srcf = x + (size_t)bc * (H * W) + (size_t)rmin * W;
        const float4* src4 = reinterpret_cast<const float4*>(srcf);
        const int total = nrows * CH4;
        for (int i = tid; i < total; i += NTHREADS) {
            int r = i / CH4;
            int c = i - r * CH4;
            float4 g = src4[r * CH4 + c];
            float hi3 = (c == CH4 - 1) ? 0.0f : __ldg(srcf + r * W + 4 * c + 4);
            __half2* row = &spack[r * SRS];
            row[skew(4 * c + 2)] = __floats2half2_rn(g.x, g.y - g.x);
            row[skew(4 * c + 3)] = __floats2half2_rn(g.y, g.z - g.y);
            row[skew(4 * c + 4)] = __floats2half2_rn(g.z, g.w - g.z);
            row[skew(4 * c + 5)] = __floats2half2_rn(g.w, hi3 - g.w);
            if (c == 0) {                 // left pads: (0,0) and (0, data[0])
                row[skew(0)] = __floats2half2_rn(0.f, 0.f);
                row[skew(1)] = __floats2half2_rn(0.f, g.x);
            }
            if (c == CH4 - 1) {           // right pad (clamp target)
                row[skew(226)] = __floats2half2_rn(0.f, 0.f);
            }
        }
    }
    __syncthreads();

    // ---- Compute: thread = (row-in-pass r, quad q); outputs x = 4q..4q+3,
    // rows ty = r and r+4; one STG.128 per pass.
    const int r  = tid / 56;     // 0..3
    const int q  = tid - r * 56; // 0..55
    const int x0 = 4 * q;
    const char* sb = (const char*)spack;

#pragma unroll 1
    for (int v = 0; v < V; ++v) {
        // 4 tabulated x-coefficients (stride-1 LDS.64, conflict-free).
        float fxj[4];
        int   saj[4];
#pragma unroll
        for (int j = 0; j < 4; ++j) {
            float2 e = xtab[v][j][q];
            fxj[j] = e.x;
            saj[j] = __float_as_int(e.y);
        }

#pragma unroll
        for (int pass = 0; pass < 2; ++pass) {
            const int ty = r + 4 * pass;
            float4 yc = ycoef[v][ty];
            const char* rb0 = sb + __float_as_int(yc.z);
            const char* rb1 = sb + __float_as_int(yc.w);

            float4 res;
            float* rp = &res.x;
#pragma unroll
            for (int j = 0; j < 4; ++j) {
                __half2 h0 = *(const __half2*)(rb0 + saj[j]);
                __half2 h1 = *(const __half2*)(rb1 + saj[j]);
                float t0 = fmaf(fxj[j], __high2float(h0), __low2float(h0));
                float t1 = fmaf(fxj[j], __high2float(h1), __low2float(h1));
                rp[j] = fmaf(t1, yc.y, t0 * yc.x);
            }
            *reinterpret_cast<float4*>(
                out + (((size_t)(v * BCN + bc)) * H + yb + ty) * W + x0) = res;
        }
    }
}

}  // namespace

extern "C" void kernel_launch(void* const* d_in, const int* in_sizes, int n_in,
                              void* d_out, int out_size) {
    const float* x    = (const float*)d_in[0];
    const float* offs = (const float*)d_in[1];
    if (n_in >= 2 && in_sizes[0] == 2 * V) {   // tolerate swapped metadata order
        const float* t = x; x = offs; offs = t;
    }
    dim3 grid(H / TILE_Y, BCN);
    shift_views_kernel<<<grid, NTHREADS>>>(x, offs, (float*)d_out);
}

// round 12
// speedup vs baseline: 1.4164x; 1.1731x over previous
#include <cuda_runtime.h>
#include <cuda_fp16.h>

// LearnableShiftViews: out[v,b,c,h,w] = separable bilinear resample of x[b,c]
// at pix = (idx + d)*size/(size-1) - 0.5 per axis, zero padding.
//
// R12 (base = R9, 53.2us, issue/L1 balanced at ~42/~39us): two safe cuts.
//  1) Diff-packed fp16 pair table (proven in R10/R11): entry p =
//     half2(a0, a1-a0), x-lerp = one fp32 fmaf. -2 FADD/output of issue.
//  2) TILE_Y 16 (was 8): halves amortized prologue + x-coeff cost and cuts
//     staging traffic from 1.5 to 1.25 input rows per output row. smem
//     19.6 KB keeps 9 blocks/SM (63 warps, occupancy unchanged).
// No xtab (R11 showed smem tables add L1 wavefronts + cost occupancy).
// Skewed addressing (addr = e + (e>>5) words) keeps quad-thread stride-4
// tap loads conflict-free. Weights/blend fp32; taps+deltas fp16.

namespace {

constexpr int H = 224;
constexpr int W = 224;
constexpr int B = 64;
constexpr int C = 3;
constexpr int BCN = B * C;     // 192
constexpr int V = 5;
constexpr int TILE_Y = 16;
constexpr int ROWS_CAP = 20;   // 16*sy + |dy|<=1 + 2 < 20
constexpr int NTHREADS = 224;  // 56 quads x 4 rows per pass; 4 passes
constexpr int CH4 = W / 4;     // 56 float4 chunks per input row
constexpr int SRS = 236;       // skewed words per packed row

__device__ __forceinline__ int skew(int e) { return e + (e >> 5); }

__global__ __launch_bounds__(NTHREADS)
void shift_views_kernel(const float* __restrict__ x,
                        const float* __restrict__ offs,
                        float* __restrict__ out) {
    __shared__ __half2 spack[ROWS_CAP * SRS];   // skewed diff pair table, 18.9 KB
    __shared__ float4  ycoef[V][TILE_Y];        // {wy0, wy1, byteoff0, byteoff1}

    const int yb  = blockIdx.x * TILE_Y;
    const int bc  = blockIdx.y;
    const int tid = threadIdx.x;
    const float sy = (float)H / (float)(H - 1);
    const float sx = (float)W / (float)(W - 1);

    // ---- Row range needed across all views (endpoints suffice; monotone).
    int rmin = H - 1, rmax = 0;
#pragma unroll
    for (int v = 0; v < V; ++v) {
        float dy = __ldg(&offs[2 * v]);
        int lo = (int)floorf(((float)yb + dy) * sy - 0.5f);
        int hi = (int)floorf(((float)(yb + TILE_Y - 1) + dy) * sy - 0.5f) + 1;
        lo = max(lo, 0);
        hi = min(hi, H - 1);
        rmin = min(rmin, lo);
        rmax = max(rmax, hi);
    }
    if (rmin > rmax) { rmin = 0; rmax = 0; }
    rmax = min(rmax, rmin + ROWS_CAP - 1);
    const int nrows = rmax - rmin + 1;

    // ---- Build y-coefficient table: one thread per (v, ty).
    if (tid < V * TILE_Y) {
        int v  = tid >> 4;
        int t  = tid & 15;
        float dy   = offs[2 * v];
        float ypix = ((float)(yb + t) + dy) * sy - 0.5f;
        float py   = floorf(ypix);
        float fy   = ypix - py;
        int   iy0  = (int)py;
        float wy0  = ((unsigned)iy0       < (unsigned)H) ? (1.0f - fy) : 0.0f;
        float wy1  = ((unsigned)(iy0 + 1) < (unsigned)H) ? fy          : 0.0f;
        int r0 = min(max(iy0,     rmin), rmax) - rmin;
        int r1 = min(max(iy0 + 1, rmin), rmax) - rmin;
        ycoef[v][t] = make_float4(wy0, wy1,
                                  __int_as_float(r0 * SRS * 4),
                                  __int_as_float(r1 * SRS * 4));
    }

    // ---- Stage + pack skewed diff table: entry p = (a0, a1-a0).
    {
        const float*  srcf = x + (size_t)bc * (H * W) + (size_t)rmin * W;
        const float4* src4 = reinterpret_cast<const float4*>(srcf);
        const int total = nrows * CH4;
        for (int i = tid; i < total; i += NTHREADS) {
            int r = i / CH4;
            int c = i - r * CH4;
            float4 g = src4[r * CH4 + c];
            float hi3 = (c == CH4 - 1) ? 0.0f : __ldg(srcf + r * W + 4 * c + 4);
            __half2* row = &spack[r * SRS];
            row[skew(4 * c + 2)] = __floats2half2_rn(g.x, g.y - g.x);
            row[skew(4 * c + 3)] = __floats2half2_rn(g.y, g.z - g.y);
            row[skew(4 * c + 4)] = __floats2half2_rn(g.z, g.w - g.z);
            row[skew(4 * c + 5)] = __floats2half2_rn(g.w, hi3 - g.w);
            if (c == 0) {                 // left pads: (0,0) and (0, data[0])
                row[skew(0)] = __floats2half2_rn(0.f, 0.f);
                row[skew(1)] = __floats2half2_rn(0.f, g.x);
            }
            if (c == CH4 - 1) {           // right pad (clamp target)
                row[skew(226)] = __floats2half2_rn(0.f, 0.f);
            }
        }
    }
    __syncthreads();

    // ---- Compute: thread = (row-in-pass r, quad q); outputs x = 4q..4q+3,
    // rows ty = r, r+4, r+8, r+12; one STG.128 per pass.
    const int r  = tid / 56;     // 0..3
    const int q  = tid - r * 56; // 0..55
    const int x0 = 4 * q;
    const char* sb = (const char*)spack;

#pragma unroll 1
    for (int v = 0; v < V; ++v) {
        const float dx = __ldg(&offs[2 * v + 1]);
        const float cx = dx * sx - 0.5f;

        // 4 x-coefficients, once per view, reused across 4 row passes (16 outs).
        float fxj[4];
        int   saj[4];
#pragma unroll
        for (int j = 0; j < 4; ++j) {
            float xpix = fmaf((float)(x0 + j), sx, cx);
            int   ix0  = __float2int_rd(xpix);
            fxj[j]     = xpix - (float)ix0;
            int   p0   = min(max(ix0 + 2, 0), 226);
            saj[j]     = skew(p0) * 4;            // skewed byte offset
        }

#pragma unroll
        for (int pass = 0; pass < 4; ++pass) {
            const int ty = r + 4 * pass;
            float4 yc = ycoef[v][ty];
            const char* rb0 = sb + __float_as_int(yc.z);
            const char* rb1 = sb + __float_as_int(yc.w);

            float4 res;
            float* rp = &res.x;
#pragma unroll
            for (int j = 0; j < 4; ++j) {
                __half2 h0 = *(const __half2*)(rb0 + saj[j]);
                __half2 h1 = *(const __half2*)(rb1 + saj[j]);
                float t0 = fmaf(fxj[j], __high2float(h0), __low2float(h0));
                float t1 = fmaf(fxj[j], __high2float(h1), __low2float(h1));
                rp[j] = fmaf(t1, yc.y, t0 * yc.x);
            }
            *reinterpret_cast<float4*>(
                out + (((size_t)(v * BCN + bc)) * H + yb + ty) * W + x0) = res;
        }
    }
}

}  // namespace

extern "C" void kernel_launch(void* const* d_in, const int* in_sizes, int n_in,
                              void* d_out, int out_size) {
    const float* x    = (const float*)d_in[0];
    const float* offs = (const float*)d_in[1];
    if (n_in >= 2 && in_sizes[0] == 2 * V) {   // tolerate swapped metadata order
        const float* t = x; x = offs; offs = t;
    }
    dim3 grid(H / TILE_Y, BCN);
    shift_views_kernel<<<grid, NTHREADS>>>(x, offs, (float*)d_out);
}